// round 2
// baseline (speedup 1.0000x reference)
#include <cuda_runtime.h>
#include <math.h>

#define BATCH 8
#define NPTS  16384
#define DIM   64
#define SPTS  2048
#define KNN   32

// ---------------- device scratch (static globals; no allocation) ----------------
__device__ float g_pn[BATCH * NPTS];            // per-point squared feature norms
__device__ int   g_nbr[BATCH * SPTS * KNN];     // knn indices
__device__ float g_wf0[64 * 64];
__device__ float g_bf0[64];
__device__ float g_wf1[64 * 64];
__device__ float g_bf1[64];
__device__ float g_wf2[128 * 64];
__device__ float g_bf2[128];

// ---------------- prep: fold BN into weights ----------------
__global__ void fold_kernel(
    const float* __restrict__ w0, const float* __restrict__ b0, const float* __restrict__ g0,
    const float* __restrict__ be0, const float* __restrict__ m0, const float* __restrict__ v0,
    const float* __restrict__ w1, const float* __restrict__ b1, const float* __restrict__ g1,
    const float* __restrict__ be1, const float* __restrict__ m1, const float* __restrict__ v1,
    const float* __restrict__ w2, const float* __restrict__ b2, const float* __restrict__ g2,
    const float* __restrict__ be2, const float* __restrict__ m2, const float* __restrict__ v2)
{
    int o = threadIdx.x;
    if (o < 64) {
        float s0 = g0[o] * rsqrtf(v0[o] + 1e-5f);
        g_bf0[o] = (b0[o] - m0[o]) * s0 + be0[o];
        for (int c = 0; c < 64; c++) g_wf0[o * 64 + c] = w0[o * 64 + c] * s0;
        float s1 = g1[o] * rsqrtf(v1[o] + 1e-5f);
        g_bf1[o] = (b1[o] - m1[o]) * s1 + be1[o];
        for (int c = 0; c < 64; c++) g_wf1[o * 64 + c] = w1[o * 64 + c] * s1;
    }
    if (o < 128) {
        float s2 = g2[o] * rsqrtf(v2[o] + 1e-5f);
        g_bf2[o] = (b2[o] - m2[o]) * s2 + be2[o];
        for (int c = 0; c < 64; c++) g_wf2[o * 64 + c] = w2[o * 64 + c] * s2;
    }
}

// ---------------- prep: point feature norms ----------------
__global__ void norms_kernel(const float* __restrict__ points)
{
    int row = blockIdx.x * 256 + threadIdx.x;   // 0 .. BATCH*NPTS-1
    const float4* p = reinterpret_cast<const float4*>(points) + (size_t)row * 16;
    float s = 0.0f;
#pragma unroll
    for (int i = 0; i < 16; i++) {
        float4 v = p[i];
        s = fmaf(v.x, v.x, s);
        s = fmaf(v.y, v.y, s);
        s = fmaf(v.z, v.z, s);
        s = fmaf(v.w, v.w, s);
    }
    g_pn[row] = s;
}

// ---------------- output part 1: new_xyz gather ----------------
__global__ void newxyz_kernel(const float* __restrict__ xyz,
                              const int* __restrict__ sidx,
                              float* __restrict__ out)
{
    int t = blockIdx.x * 256 + threadIdx.x;     // 0 .. 49151
    int c  = t % 3;
    int bs = t / 3;
    int b  = bs >> 11;          // /2048
    int s  = bs & 2047;
    out[t] = xyz[((size_t)b * NPTS + sidx[s]) * 3 + c];
}

// ---------------- kernel A: fused distance + top-32 (per-query heap) ----------------
// grid (64, 8), 256 threads. Each block: 32 queries x all 16384 points.
// Rank by e = |p|^2 - 2 q.p  (the |q|^2 term is per-query constant: order-preserving).
// smem float offsets:
//   qsf   [0,    2048)   query features * -2, layout [q][64]
//   ps4   [2048, 10752)  point tile, float4 layout [128][17] (pad for bank-free LDS.128)
//   pn_s  [10752,10880)  point tile norms
//   cd    [10880,14976)  candidate dists  [32][128]
//   ci    [14976,19072)  candidate idx    [32][128]
//   hd    [19072,20128)  heaps dist [32][33]
//   hi    [20128,21184)  heaps idx  [32][33]
//   cnt   [21184,21216)
//   qsid  [21216,21248)
#define KNN_SMEM_FLOATS 21248

__global__ void __launch_bounds__(256) knn_kernel(const float* __restrict__ points,
                                                  const int* __restrict__ sample_idx)
{
    extern __shared__ float sm[];
    float*  qsf  = sm;
    float4* qs4  = reinterpret_cast<float4*>(sm);
    float4* ps4  = reinterpret_cast<float4*>(sm + 2048);
    float*  pn_s = sm + 10752;
    float*  cd   = sm + 10880;
    int*    ci   = reinterpret_cast<int*>(sm + 14976);
    float*  hd   = sm + 19072;
    int*    hi   = reinterpret_cast<int*>(sm + 20128);
    int*    cnt  = reinterpret_cast<int*>(sm + 21184);
    int*    qsid = reinterpret_cast<int*>(sm + 21216);

    const int tid = threadIdx.x;
    const int w   = tid >> 5;
    const int tp  = tid & 31;
    const int b   = blockIdx.y;
    const int qbase = blockIdx.x * 32;
    const float* Pb = points + (size_t)b * NPTS * DIM;

    if (tid < 32) { qsid[tid] = sample_idx[qbase + tid]; cnt[tid] = 0; }
    __syncthreads();

    // stage -2*query features
    for (int e = tid; e < 32 * 64; e += 256) {
        int q = e >> 6, k = e & 63;
        qsf[q * 64 + k] = -2.0f * Pb[(size_t)qsid[q] * 64 + k];
    }
    // init heaps
    for (int e = tid; e < 32 * 32; e += 256) {
        int q = e >> 5, x = e & 31;
        hd[q * 33 + x] = 3.4e38f;
        hi[q * 33 + x] = 0;
    }
    __syncthreads();

    for (int pb = 0; pb < NPTS; pb += 128) {
        // stage point tile (coalesced global -> padded smem)
        const float4* Pg4 = reinterpret_cast<const float4*>(Pb + (size_t)pb * 64);
        for (int e = tid; e < 128 * 16; e += 256) {
            int r = e >> 4, d4 = e & 15;
            ps4[r * 17 + d4] = Pg4[r * 16 + d4];
        }
        if (tid < 128) pn_s[tid] = g_pn[b * NPTS + pb + tid];
        __syncthreads();

        // each thread: 4 queries (warp-broadcast) x 4 points (stride-32 lanes)
        float acc[4][4];
#pragma unroll
        for (int i = 0; i < 4; i++) {
            float pn = pn_s[tp + 32 * i];
#pragma unroll
            for (int j = 0; j < 4; j++) acc[i][j] = pn;
        }
#pragma unroll
        for (int k4 = 0; k4 < 16; k4++) {
            float4 pv0 = ps4[(tp      ) * 17 + k4];
            float4 pv1 = ps4[(tp + 32 ) * 17 + k4];
            float4 pv2 = ps4[(tp + 64 ) * 17 + k4];
            float4 pv3 = ps4[(tp + 96 ) * 17 + k4];
#pragma unroll
            for (int j = 0; j < 4; j++) {
                float4 qv = qs4[(w * 4 + j) * 16 + k4];
                acc[0][j] = fmaf(qv.x, pv0.x, acc[0][j]);
                acc[0][j] = fmaf(qv.y, pv0.y, acc[0][j]);
                acc[0][j] = fmaf(qv.z, pv0.z, acc[0][j]);
                acc[0][j] = fmaf(qv.w, pv0.w, acc[0][j]);
                acc[1][j] = fmaf(qv.x, pv1.x, acc[1][j]);
                acc[1][j] = fmaf(qv.y, pv1.y, acc[1][j]);
                acc[1][j] = fmaf(qv.z, pv1.z, acc[1][j]);
                acc[1][j] = fmaf(qv.w, pv1.w, acc[1][j]);
                acc[2][j] = fmaf(qv.x, pv2.x, acc[2][j]);
                acc[2][j] = fmaf(qv.y, pv2.y, acc[2][j]);
                acc[2][j] = fmaf(qv.z, pv2.z, acc[2][j]);
                acc[2][j] = fmaf(qv.w, pv2.w, acc[2][j]);
                acc[3][j] = fmaf(qv.x, pv3.x, acc[3][j]);
                acc[3][j] = fmaf(qv.y, pv3.y, acc[3][j]);
                acc[3][j] = fmaf(qv.z, pv3.z, acc[3][j]);
                acc[3][j] = fmaf(qv.w, pv3.w, acc[3][j]);
            }
        }

        // threshold filter -> candidate buffer (<=128 per query per tile by construction)
#pragma unroll
        for (int j = 0; j < 4; j++) {
            int q = w * 4 + j;
            float thr = hd[q * 33];
#pragma unroll
            for (int i = 0; i < 4; i++) {
                if (acc[i][j] < thr) {
                    int pos = atomicAdd(&cnt[q], 1);
                    cd[q * 128 + pos] = acc[i][j];
                    ci[q * 128 + pos] = pb + tp + 32 * i;
                }
            }
        }
        __syncthreads();

        // serial heap insertion, one thread per query
        if (tid < 32) {
            int q = tid;
            int n = cnt[q];
            float* H  = hd + q * 33;
            int*   HI = hi + q * 33;
            for (int c = 0; c < n; c++) {
                float e = cd[q * 128 + c];
                if (e < H[0]) {
                    H[0]  = e;
                    HI[0] = ci[q * 128 + c];
                    int i2 = 0;
                    while (true) {
                        int ch = 2 * i2 + 1;
                        if (ch >= 32) break;
                        if (ch + 1 < 32 && H[ch + 1] > H[ch]) ch++;
                        if (H[ch] > H[i2]) {
                            float td = H[ch]; H[ch] = H[i2]; H[i2] = td;
                            int   ti = HI[ch]; HI[ch] = HI[i2]; HI[i2] = ti;
                            i2 = ch;
                        } else break;
                    }
                }
            }
            cnt[q] = 0;
        }
        __syncthreads();
    }

    // write neighbor index sets
    for (int e = tid; e < 32 * 32; e += 256) {
        int q = e >> 5, x = e & 31;
        g_nbr[((size_t)(b * SPTS + qbase + q)) * 32 + x] = hi[q * 33 + x];
    }
}

// ---------------- kernel B: gather + 3-layer MLP + max-pool ----------------
// warp per query; lane = neighbor row; x in registers, weights broadcast from smem.
#define MLP_SMEM_FLOATS 16640

__device__ __forceinline__ void mlp_layer64(const float* __restrict__ xin,
                                            float* __restrict__ yout,
                                            const float* __restrict__ swp,
                                            const float* __restrict__ sbp)
{
    const float4* sw4 = reinterpret_cast<const float4*>(swp);
    for (int oc = 0; oc < 8; oc++) {
        float acc[8];
#pragma unroll
        for (int j = 0; j < 8; j++) acc[j] = sbp[oc * 8 + j];
#pragma unroll
        for (int k4 = 0; k4 < 16; k4++) {
            float x0 = xin[4 * k4], x1 = xin[4 * k4 + 1], x2 = xin[4 * k4 + 2], x3 = xin[4 * k4 + 3];
#pragma unroll
            for (int j = 0; j < 8; j++) {
                float4 wv = sw4[(oc * 8 + j) * 16 + k4];
                acc[j] = fmaf(x0, wv.x, acc[j]);
                acc[j] = fmaf(x1, wv.y, acc[j]);
                acc[j] = fmaf(x2, wv.z, acc[j]);
                acc[j] = fmaf(x3, wv.w, acc[j]);
            }
        }
#pragma unroll
        for (int j = 0; j < 8; j++) yout[oc * 8 + j] = fmaxf(acc[j], 0.0f);
    }
}

__global__ void __launch_bounds__(256) mlp_kernel(const float* __restrict__ points,
                                                  float* __restrict__ out_np)
{
    extern __shared__ float sm[];
    float* sw0 = sm;
    float* sw1 = sm + 4096;
    float* sw2 = sm + 8192;
    float* sb0 = sm + 16384;
    float* sb1 = sm + 16448;
    float* sb2 = sm + 16512;

    const int tid = threadIdx.x;
    for (int e = tid; e < 4096; e += 256) {
        sw0[e] = g_wf0[e];
        sw1[e] = g_wf1[e];
        sw2[e] = g_wf2[e];
        sw2[e + 4096] = g_wf2[e + 4096];
    }
    if (tid < 64)  { sb0[tid] = g_bf0[tid]; sb1[tid] = g_bf1[tid]; }
    if (tid < 128) sb2[tid] = g_bf2[tid];
    __syncthreads();

    const int w    = tid >> 5;
    const int lane = tid & 31;
    const int qg   = blockIdx.x * 8 + w;   // 0 .. 16383
    const int b    = qg >> 11;

    int nbr = g_nbr[(size_t)qg * 32 + lane];
    const float4* xr = reinterpret_cast<const float4*>(points + ((size_t)b * NPTS + nbr) * 64);

    float x[64];
#pragma unroll
    for (int k4 = 0; k4 < 16; k4++) {
        float4 v = xr[k4];
        x[4 * k4] = v.x; x[4 * k4 + 1] = v.y; x[4 * k4 + 2] = v.z; x[4 * k4 + 3] = v.w;
    }

    float y[64];
    mlp_layer64(x, y, sw0, sb0);   // layer 0: x -> y
    mlp_layer64(y, x, sw1, sb1);   // layer 1: y -> x

    // layer 2 (64 -> 128) fused with max over 32 neighbor rows (lanes)
    const float4* sw24 = reinterpret_cast<const float4*>(sw2);
    for (int oc = 0; oc < 16; oc++) {
        float acc[8];
#pragma unroll
        for (int j = 0; j < 8; j++) acc[j] = sb2[oc * 8 + j];
#pragma unroll
        for (int k4 = 0; k4 < 16; k4++) {
            float x0 = x[4 * k4], x1 = x[4 * k4 + 1], x2 = x[4 * k4 + 2], x3 = x[4 * k4 + 3];
#pragma unroll
            for (int j = 0; j < 8; j++) {
                float4 wv = sw24[(oc * 8 + j) * 16 + k4];
                acc[j] = fmaf(x0, wv.x, acc[j]);
                acc[j] = fmaf(x1, wv.y, acc[j]);
                acc[j] = fmaf(x2, wv.z, acc[j]);
                acc[j] = fmaf(x3, wv.w, acc[j]);
            }
        }
#pragma unroll
        for (int j = 0; j < 8; j++) {
            float v = fmaxf(acc[j], 0.0f);
#pragma unroll
            for (int off = 16; off > 0; off >>= 1)
                v = fmaxf(v, __shfl_xor_sync(0xffffffffu, v, off));
            if (lane == 0) out_np[(size_t)qg * 128 + oc * 8 + j] = v;
        }
    }
}

// ---------------- launch ----------------
extern "C" void kernel_launch(void* const* d_in, const int* in_sizes, int n_in,
                              void* d_out, int out_size)
{
    const float* xyz    = (const float*)d_in[0];
    const float* points = (const float*)d_in[1];
    const int*   sidx   = (const int*)  d_in[2];
    const float* w0 = (const float*)d_in[3];
    const float* b0 = (const float*)d_in[4];
    const float* g0 = (const float*)d_in[5];
    const float* be0= (const float*)d_in[6];
    const float* m0 = (const float*)d_in[7];
    const float* v0 = (const float*)d_in[8];
    const float* w1 = (const float*)d_in[9];
    const float* b1 = (const float*)d_in[10];
    const float* g1 = (const float*)d_in[11];
    const float* be1= (const float*)d_in[12];
    const float* m1 = (const float*)d_in[13];
    const float* v1 = (const float*)d_in[14];
    const float* w2 = (const float*)d_in[15];
    const float* b2 = (const float*)d_in[16];
    const float* g2 = (const float*)d_in[17];
    const float* be2= (const float*)d_in[18];
    const float* m2 = (const float*)d_in[19];
    const float* v2 = (const float*)d_in[20];
    float* out = (float*)d_out;

    cudaFuncSetAttribute(knn_kernel, cudaFuncAttributeMaxDynamicSharedMemorySize,
                         KNN_SMEM_FLOATS * 4);
    cudaFuncSetAttribute(mlp_kernel, cudaFuncAttributeMaxDynamicSharedMemorySize,
                         MLP_SMEM_FLOATS * 4);

    fold_kernel<<<1, 128>>>(w0, b0, g0, be0, m0, v0,
                            w1, b1, g1, be1, m1, v1,
                            w2, b2, g2, be2, m2, v2);
    norms_kernel<<<(BATCH * NPTS) / 256, 256>>>(points);
    newxyz_kernel<<<(BATCH * SPTS * 3) / 256, 256>>>(xyz, sidx, out);
    knn_kernel<<<dim3(SPTS / 32, BATCH), 256, KNN_SMEM_FLOATS * 4>>>(points, sidx);
    mlp_kernel<<<(BATCH * SPTS) / 8, 256, MLP_SMEM_FLOATS * 4>>>(
        points, out + (size_t)BATCH * SPTS * 3);
}

// round 17
// speedup vs baseline: 1.5485x; 1.5485x over previous
#include <cuda_runtime.h>
#include <math.h>

#define BATCH 8
#define NPTS  16384
#define DIM   64
#define SPTS  2048
#define KNN   32

// ---------------- device scratch (static globals; no allocation) ----------------
__device__ float g_pn[BATCH * NPTS];            // per-point squared feature norms
__device__ int   g_nbr[BATCH * SPTS * KNN];     // knn indices
__device__ float g_wf0[64 * 64];
__device__ float g_bf0[64];
__device__ float g_wf1[64 * 64];
__device__ float g_bf1[64];
__device__ float g_wf2[128 * 64];
__device__ float g_bf2[128];

// ---------------- prep: fold BN into weights ----------------
__global__ void fold_kernel(
    const float* __restrict__ w0, const float* __restrict__ b0, const float* __restrict__ g0,
    const float* __restrict__ be0, const float* __restrict__ m0, const float* __restrict__ v0,
    const float* __restrict__ w1, const float* __restrict__ b1, const float* __restrict__ g1,
    const float* __restrict__ be1, const float* __restrict__ m1, const float* __restrict__ v1,
    const float* __restrict__ w2, const float* __restrict__ b2, const float* __restrict__ g2,
    const float* __restrict__ be2, const float* __restrict__ m2, const float* __restrict__ v2)
{
    int o = threadIdx.x;
    if (o < 64) {
        float s0 = g0[o] * rsqrtf(v0[o] + 1e-5f);
        g_bf0[o] = (b0[o] - m0[o]) * s0 + be0[o];
        for (int c = 0; c < 64; c++) g_wf0[o * 64 + c] = w0[o * 64 + c] * s0;
        float s1 = g1[o] * rsqrtf(v1[o] + 1e-5f);
        g_bf1[o] = (b1[o] - m1[o]) * s1 + be1[o];
        for (int c = 0; c < 64; c++) g_wf1[o * 64 + c] = w1[o * 64 + c] * s1;
    }
    if (o < 128) {
        float s2 = g2[o] * rsqrtf(v2[o] + 1e-5f);
        g_bf2[o] = (b2[o] - m2[o]) * s2 + be2[o];
        for (int c = 0; c < 64; c++) g_wf2[o * 64 + c] = w2[o * 64 + c] * s2;
    }
}

// ---------------- prep: point feature norms ----------------
__global__ void norms_kernel(const float* __restrict__ points)
{
    int row = blockIdx.x * 256 + threadIdx.x;   // 0 .. BATCH*NPTS-1
    const float4* p = reinterpret_cast<const float4*>(points) + (size_t)row * 16;
    float s = 0.0f;
#pragma unroll
    for (int i = 0; i < 16; i++) {
        float4 v = p[i];
        s = fmaf(v.x, v.x, s);
        s = fmaf(v.y, v.y, s);
        s = fmaf(v.z, v.z, s);
        s = fmaf(v.w, v.w, s);
    }
    g_pn[row] = s;
}

// ---------------- output part 1: new_xyz gather ----------------
__global__ void newxyz_kernel(const float* __restrict__ xyz,
                              const int* __restrict__ sidx,
                              float* __restrict__ out)
{
    int t = blockIdx.x * 256 + threadIdx.x;     // 0 .. 49151
    int c  = t % 3;
    int bs = t / 3;
    int b  = bs >> 11;          // /2048
    int s  = bs & 2047;
    out[t] = xyz[((size_t)b * NPTS + sidx[s]) * 3 + c];
}

// ---------------- kernel A: fused distance + top-32, per-warp heaps ----------------
// grid (64, 8), 256 threads. Block: 32 queries x 16384 points; warp owns 4 queries.
// Rank by e = |p|^2 - 2 q.p  (|q|^2 per-query constant, order-preserving).
// smem float offsets:
//   qsf   [0,     2048)   query features * -2, [q][64]
//   ps4   [2048,  10752)  point tile, float4 [128][17] (pad -> conflict-free LDS.128)
//   pn_s  [10752, 10880)  point tile norms
//   hd    [10880, 11936)  heaps dist [32][33]
//   hi    [11936, 12992)  heaps idx  [32][33]
//   qsid  [12992, 13024)
#define KNN_SMEM_FLOATS 13024

__device__ __forceinline__ void heap_sift_down(float* H, int* HI)
{
    int p = 0;
    while (true) {
        int c = 2 * p + 1;
        if (c >= 32) break;
        if (c + 1 < 32 && H[c + 1] > H[c]) c++;
        if (H[c] > H[p]) {
            float td = H[c]; H[c] = H[p]; H[p] = td;
            int   ti = HI[c]; HI[c] = HI[p]; HI[p] = ti;
            p = c;
        } else break;
    }
}

__global__ void __launch_bounds__(256, 4) knn_kernel(const float* __restrict__ points,
                                                     const int* __restrict__ sample_idx)
{
    extern __shared__ float sm[];
    float4* qs4  = reinterpret_cast<float4*>(sm);
    float*  qsf  = sm;
    float4* ps4  = reinterpret_cast<float4*>(sm + 2048);
    float*  pn_s = sm + 10752;
    float*  hd   = sm + 10880;
    int*    hi   = reinterpret_cast<int*>(sm + 11936);
    int*    qsid = reinterpret_cast<int*>(sm + 12992);

    const int tid = threadIdx.x;
    const int w   = tid >> 5;
    const int tp  = tid & 31;
    const int b   = blockIdx.y;
    const int qbase = blockIdx.x * 32;
    const float* Pb = points + (size_t)b * NPTS * DIM;

    if (tid < 32) qsid[tid] = sample_idx[qbase + tid];
    __syncthreads();

    // stage -2*query features
    for (int e = tid; e < 32 * 64; e += 256) {
        int q = e >> 6, k = e & 63;
        qsf[q * 64 + k] = -2.0f * Pb[(size_t)qsid[q] * 64 + k];
    }

    // per-warp heap threshold registers (uniform within warp)
    float thr[4];
#pragma unroll
    for (int j = 0; j < 4; j++) thr[j] = 3.4e38f;

    for (int pb = 0; pb < NPTS; pb += 128) {
        __syncthreads();   // previous compute (all warps) done before tile overwrite
        const float4* Pg4 = reinterpret_cast<const float4*>(Pb + (size_t)pb * 64);
        for (int e = tid; e < 128 * 16; e += 256) {
            int r = e >> 4, d4 = e & 15;
            ps4[r * 17 + d4] = Pg4[r * 16 + d4];
        }
        if (tid < 128) pn_s[tid] = g_pn[b * NPTS + pb + tid];
        __syncthreads();

        // each thread: 4 queries (warp-broadcast) x 4 points (stride-32 lanes)
        float acc[4][4];
#pragma unroll
        for (int i = 0; i < 4; i++) {
            float pn = pn_s[tp + 32 * i];
#pragma unroll
            for (int j = 0; j < 4; j++) acc[i][j] = pn;
        }
#pragma unroll
        for (int k4 = 0; k4 < 16; k4++) {
            float4 pv0 = ps4[(tp      ) * 17 + k4];
            float4 pv1 = ps4[(tp + 32 ) * 17 + k4];
            float4 pv2 = ps4[(tp + 64 ) * 17 + k4];
            float4 pv3 = ps4[(tp + 96 ) * 17 + k4];
#pragma unroll
            for (int j = 0; j < 4; j++) {
                float4 qv = qs4[(w * 4 + j) * 16 + k4];
                acc[0][j] = fmaf(qv.x, pv0.x, acc[0][j]);
                acc[0][j] = fmaf(qv.y, pv0.y, acc[0][j]);
                acc[0][j] = fmaf(qv.z, pv0.z, acc[0][j]);
                acc[0][j] = fmaf(qv.w, pv0.w, acc[0][j]);
                acc[1][j] = fmaf(qv.x, pv1.x, acc[1][j]);
                acc[1][j] = fmaf(qv.y, pv1.y, acc[1][j]);
                acc[1][j] = fmaf(qv.z, pv1.z, acc[1][j]);
                acc[1][j] = fmaf(qv.w, pv1.w, acc[1][j]);
                acc[2][j] = fmaf(qv.x, pv2.x, acc[2][j]);
                acc[2][j] = fmaf(qv.y, pv2.y, acc[2][j]);
                acc[2][j] = fmaf(qv.z, pv2.z, acc[2][j]);
                acc[2][j] = fmaf(qv.w, pv2.w, acc[2][j]);
                acc[3][j] = fmaf(qv.x, pv3.x, acc[3][j]);
                acc[3][j] = fmaf(qv.y, pv3.y, acc[3][j]);
                acc[3][j] = fmaf(qv.z, pv3.z, acc[3][j]);
                acc[3][j] = fmaf(qv.w, pv3.w, acc[3][j]);
            }
        }

        // per-warp top-k maintenance: warp w owns queries 4w..4w+3 exclusively.
#pragma unroll
        for (int j = 0; j < 4; j++) {
            const int q = (w << 2) + j;
            float* H  = hd + q * 33;
            int*   HI = hi + q * 33;
            int i0 = 0;
            if (pb == 0) {
                // bulk-fill heap with the 32 lane distances of i=0, then heapify
                H[tp]  = acc[0][j];
                HI[tp] = tp;
                __syncwarp();
                if (tp == 0) {
                    for (int s = 15; s >= 0; s--) {     // bottom-up heapify (last internal = 15)
                        int p = s;
                        while (true) {
                            int c = 2 * p + 1;
                            if (c >= 32) break;
                            if (c + 1 < 32 && H[c + 1] > H[c]) c++;
                            if (H[c] > H[p]) {
                                float td = H[c]; H[c] = H[p]; H[p] = td;
                                int   ti = HI[c]; HI[c] = HI[p]; HI[p] = ti;
                                p = c;
                            } else break;
                        }
                    }
                }
                __syncwarp();
                thr[j] = H[0];
                i0 = 1;
            }
            for (int i = i0; i < 4; i++) {
                unsigned m = __ballot_sync(0xffffffffu, acc[i][j] < thr[j]);
                while (m) {
                    int src = __ffs(m) - 1;
                    m &= m - 1;
                    float v = __shfl_sync(0xffffffffu, acc[i][j], src);
                    if (v < thr[j]) {
                        if (tp == 0) {
                            H[0]  = v;
                            HI[0] = pb + src + 32 * i;
                            heap_sift_down(H, HI);
                        }
                        __syncwarp();
                        thr[j] = H[0];
                    }
                }
            }
        }
    }

    __syncthreads();
    // write neighbor index sets
    for (int e = tid; e < 32 * 32; e += 256) {
        int q = e >> 5, x = e & 31;
        g_nbr[((size_t)(b * SPTS + qbase + q)) * 32 + x] = hi[q * 33 + x];
    }
}

// ---------------- kernel B: gather + 3-layer MLP + max-pool ----------------
// warp per query; lane = neighbor row; x in registers, weights broadcast from smem.
#define MLP_SMEM_FLOATS 16640

__device__ __forceinline__ void mlp_layer64(const float* __restrict__ xin,
                                            float* __restrict__ yout,
                                            const float* __restrict__ swp,
                                            const float* __restrict__ sbp)
{
    const float4* sw4 = reinterpret_cast<const float4*>(swp);
    for (int oc = 0; oc < 8; oc++) {
        float acc[8];
#pragma unroll
        for (int j = 0; j < 8; j++) acc[j] = sbp[oc * 8 + j];
#pragma unroll
        for (int k4 = 0; k4 < 16; k4++) {
            float x0 = xin[4 * k4], x1 = xin[4 * k4 + 1], x2 = xin[4 * k4 + 2], x3 = xin[4 * k4 + 3];
#pragma unroll
            for (int j = 0; j < 8; j++) {
                float4 wv = sw4[(oc * 8 + j) * 16 + k4];
                acc[j] = fmaf(x0, wv.x, acc[j]);
                acc[j] = fmaf(x1, wv.y, acc[j]);
                acc[j] = fmaf(x2, wv.z, acc[j]);
                acc[j] = fmaf(x3, wv.w, acc[j]);
            }
        }
#pragma unroll
        for (int j = 0; j < 8; j++) yout[oc * 8 + j] = fmaxf(acc[j], 0.0f);
    }
}

__global__ void __launch_bounds__(256) mlp_kernel(const float* __restrict__ points,
                                                  float* __restrict__ out_np)
{
    extern __shared__ float sm[];
    float* sw0 = sm;
    float* sw1 = sm + 4096;
    float* sw2 = sm + 8192;
    float* sb0 = sm + 16384;
    float* sb1 = sm + 16448;
    float* sb2 = sm + 16512;

    const int tid = threadIdx.x;
    for (int e = tid; e < 4096; e += 256) {
        sw0[e] = g_wf0[e];
        sw1[e] = g_wf1[e];
        sw2[e] = g_wf2[e];
        sw2[e + 4096] = g_wf2[e + 4096];
    }
    if (tid < 64)  { sb0[tid] = g_bf0[tid]; sb1[tid] = g_bf1[tid]; }
    if (tid < 128) sb2[tid] = g_bf2[tid];
    __syncthreads();

    const int w    = tid >> 5;
    const int lane = tid & 31;
    const int qg   = blockIdx.x * 8 + w;   // 0 .. 16383
    const int b    = qg >> 11;

    int nbr = g_nbr[(size_t)qg * 32 + lane];
    const float4* xr = reinterpret_cast<const float4*>(points + ((size_t)b * NPTS + nbr) * 64);

    float x[64];
#pragma unroll
    for (int k4 = 0; k4 < 16; k4++) {
        float4 v = xr[k4];
        x[4 * k4] = v.x; x[4 * k4 + 1] = v.y; x[4 * k4 + 2] = v.z; x[4 * k4 + 3] = v.w;
    }

    float y[64];
    mlp_layer64(x, y, sw0, sb0);   // layer 0: x -> y
    mlp_layer64(y, x, sw1, sb1);   // layer 1: y -> x

    // layer 2 (64 -> 128) fused with max over 32 neighbor rows (lanes)
    const float4* sw24 = reinterpret_cast<const float4*>(sw2);
    for (int oc = 0; oc < 16; oc++) {
        float acc[8];
#pragma unroll
        for (int j = 0; j < 8; j++) acc[j] = sb2[oc * 8 + j];
#pragma unroll
        for (int k4 = 0; k4 < 16; k4++) {
            float x0 = x[4 * k4], x1 = x[4 * k4 + 1], x2 = x[4 * k4 + 2], x3 = x[4 * k4 + 3];
#pragma unroll
            for (int j = 0; j < 8; j++) {
                float4 wv = sw24[(oc * 8 + j) * 16 + k4];
                acc[j] = fmaf(x0, wv.x, acc[j]);
                acc[j] = fmaf(x1, wv.y, acc[j]);
                acc[j] = fmaf(x2, wv.z, acc[j]);
                acc[j] = fmaf(x3, wv.w, acc[j]);
            }
        }
#pragma unroll
        for (int j = 0; j < 8; j++) {
            float v = fmaxf(acc[j], 0.0f);
#pragma unroll
            for (int off = 16; off > 0; off >>= 1)
                v = fmaxf(v, __shfl_xor_sync(0xffffffffu, v, off));
            if (lane == 0) out_np[(size_t)qg * 128 + oc * 8 + j] = v;
        }
    }
}

// ---------------- launch ----------------
extern "C" void kernel_launch(void* const* d_in, const int* in_sizes, int n_in,
                              void* d_out, int out_size)
{
    const float* xyz    = (const float*)d_in[0];
    const float* points = (const float*)d_in[1];
    const int*   sidx   = (const int*)  d_in[2];
    const float* w0 = (const float*)d_in[3];
    const float* b0 = (const float*)d_in[4];
    const float* g0 = (const float*)d_in[5];
    const float* be0= (const float*)d_in[6];
    const float* m0 = (const float*)d_in[7];
    const float* v0 = (const float*)d_in[8];
    const float* w1 = (const float*)d_in[9];
    const float* b1 = (const float*)d_in[10];
    const float* g1 = (const float*)d_in[11];
    const float* be1= (const float*)d_in[12];
    const float* m1 = (const float*)d_in[13];
    const float* v1 = (const float*)d_in[14];
    const float* w2 = (const float*)d_in[15];
    const float* b2 = (const float*)d_in[16];
    const float* g2 = (const float*)d_in[17];
    const float* be2= (const float*)d_in[18];
    const float* m2 = (const float*)d_in[19];
    const float* v2 = (const float*)d_in[20];
    float* out = (float*)d_out;

    cudaFuncSetAttribute(knn_kernel, cudaFuncAttributeMaxDynamicSharedMemorySize,
                         KNN_SMEM_FLOATS * 4);
    cudaFuncSetAttribute(mlp_kernel, cudaFuncAttributeMaxDynamicSharedMemorySize,
                         MLP_SMEM_FLOATS * 4);

    fold_kernel<<<1, 128>>>(w0, b0, g0, be0, m0, v0,
                            w1, b1, g1, be1, m1, v1,
                            w2, b2, g2, be2, m2, v2);
    norms_kernel<<<(BATCH * NPTS) / 256, 256>>>(points);
    newxyz_kernel<<<(BATCH * SPTS * 3) / 256, 256>>>(xyz, sidx, out);
    knn_kernel<<<dim3(SPTS / 32, BATCH), 256, KNN_SMEM_FLOATS * 4>>>(points, sidx);
    mlp_kernel<<<(BATCH * SPTS) / 8, 256, MLP_SMEM_FLOATS * 4>>>(
        points, out + (size_t)BATCH * SPTS * 3);
}